// round 5
// baseline (speedup 1.0000x reference)
#include <cuda_runtime.h>
#include <cstdint>

// CSR SpMM, sum-reduce: out[r,:] = sum_{e in row r} value[e] * other[col[e],:]
// N_ROWS=100000, DEG=16 (fixed), F=64, fp32. rowptr/col are INT32.
//
// L2-gather-bound: 1.6M edges x 256B = 410MB of L2 reads (`other` = 25.6MB,
// resident in 126MB L2; DRAM carries only compulsory ~70MB).
// R3 showed regs=32 strangled MLP (issue=32%, L2=61%). This version forces
// 8 independent float4 gathers in flight per thread via explicit batching
// and a 3-CTA launch bound (regs budget ~85): in-flight bytes/SM ~100KB >>
// ~21KB needed to cover L2 latency.
//
// Layout: 16 threads per row, each owning one float4 (4 features).
// blockDim = (16, 16) -> 256 threads, 16 rows per block.
// Each edge gather: 16 lanes x 16B = one contiguous 256B row of `other`.

static constexpr int F4 = 16;       // float4 groups per row (F=64)
static constexpr int ROWS_PER_BLK = 16;
static constexpr int BATCH = 8;     // gathers in flight per thread

__global__ __launch_bounds__(256, 3) void spmm_kernel(
    const int* __restrict__ rowptr,
    const int* __restrict__ col,
    const float* __restrict__ value,
    const float4* __restrict__ other,   // [N_COLS * 16] float4
    float4* __restrict__ out,           // [N_ROWS * 16] float4
    int n_rows)
{
    const int row = blockIdx.x * ROWS_PER_BLK + threadIdx.y;
    if (row >= n_rows) return;
    const int f = threadIdx.x;          // 0..15

    const int start = rowptr[row];
    const int deg   = rowptr[row + 1] - start;

    float4 acc = make_float4(0.f, 0.f, 0.f, 0.f);

    if (deg == 16) {
        // Two batches of 8: prefetch indices/values, launch 8 independent
        // 16B gathers into live registers, then reduce. Keeps 8 LDG.E.128
        // outstanding per thread (4KB/warp in flight).
#pragma unroll
        for (int b = 0; b < 16 / BATCH; ++b) {
            const int base = start + b * BATCH;
            int   c[BATCH];
            float v[BATCH];
#pragma unroll
            for (int k = 0; k < BATCH; ++k) {
                c[k] = __ldg(&col[base + k]);
                v[k] = __ldg(&value[base + k]);
            }
            float4 x[BATCH];
#pragma unroll
            for (int k = 0; k < BATCH; ++k) {
                x[k] = __ldg(&other[(long long)c[k] * F4 + f]);
            }
#pragma unroll
            for (int k = 0; k < BATCH; ++k) {
                acc.x = fmaf(v[k], x[k].x, acc.x);
                acc.y = fmaf(v[k], x[k].y, acc.y);
                acc.z = fmaf(v[k], x[k].z, acc.z);
                acc.w = fmaf(v[k], x[k].w, acc.w);
            }
        }
    } else {
        for (int e = start; e < start + deg; ++e) {
            const int   c = __ldg(&col[e]);
            const float v = __ldg(&value[e]);
            const float4 x = __ldg(&other[(long long)c * F4 + f]);
            acc.x = fmaf(v, x.x, acc.x);
            acc.y = fmaf(v, x.y, acc.y);
            acc.z = fmaf(v, x.z, acc.z);
            acc.w = fmaf(v, x.w, acc.w);
        }
    }

    out[(long long)row * F4 + f] = acc;
}

extern "C" void kernel_launch(void* const* d_in, const int* in_sizes, int n_in,
                              void* d_out, int out_size)
{
    // metadata order: rowptr (int32, N_ROWS+1), col (int32, E), value (f32, E), other (f32, N_COLS*F)
    const int*    rowptr = (const int*)d_in[0];
    const int*    col    = (const int*)d_in[1];
    const float*  value  = (const float*)d_in[2];
    const float4* other  = (const float4*)d_in[3];
    float4*       out    = (float4*)d_out;

    const int n_rows = in_sizes[0] - 1;

    dim3 block(F4, ROWS_PER_BLK);
    dim3 grid((n_rows + ROWS_PER_BLK - 1) / ROWS_PER_BLK);
    spmm_kernel<<<grid, block>>>(rowptr, col, value, other, out, n_rows);
}

// round 6
// speedup vs baseline: 1.0954x; 1.0954x over previous
#include <cuda_runtime.h>
#include <cstdint>

// CSR SpMM, sum-reduce: out[r,:] = sum_e value[e] * other[col[e],:]
// N_ROWS=100000, DEG=16 (fixed), F=64, fp32. rowptr/col INT32.
//
// L2-gather-bound (~410MB of L2 reads; `other` resident in 126MB L2).
// R3 (regs=32, occ=87%): 27.1us, MLP ~2/thread. R4 (regs=79, occ=32%): 29.4us —
// occupancy trade failed. R5: middle point + LSU instruction-count cut:
//  - metadata loaded as int4/float4 (8 LDG/warp instead of 32)
//  - 4 gathers in flight per thread, all indices pre-resident so batches overlap
//  - regs capped ~50 (min 5 CTAs/SM -> ~40 warps/SM)

static constexpr int F4 = 16;       // float4 groups per row (F=64)
static constexpr int ROWS_PER_BLK = 16;

__global__ __launch_bounds__(256, 5) void spmm_kernel(
    const int* __restrict__ rowptr,
    const int* __restrict__ col,
    const float* __restrict__ value,
    const float4* __restrict__ other,   // [N_COLS * 16] float4
    float4* __restrict__ out,           // [N_ROWS * 16] float4
    int n_rows)
{
    const int row = blockIdx.x * ROWS_PER_BLK + threadIdx.y;
    if (row >= n_rows) return;
    const int f = threadIdx.x;          // 0..15

    const int start = rowptr[row];
    const int deg   = rowptr[row + 1] - start;

    float4 acc = make_float4(0.f, 0.f, 0.f, 0.f);

    if (deg == 16 && (start & 3) == 0) {
        // Vectorized metadata: 4x int4 + 4x float4 (64B-aligned since start%4==0).
        const int4*   c4 = (const int4*)(col + start);
        const float4* v4 = (const float4*)(value + start);

        int4   c[4];
        float4 v[4];
#pragma unroll
        for (int b = 0; b < 4; ++b) {
            c[b] = __ldg(&c4[b]);
            v[b] = __ldg(&v4[b]);
        }

        // 4 batches of 4 independent gathers; batch b+1 gathers depend only on
        // pre-resident indices, so they overlap batch b's scoreboard wait.
#pragma unroll
        for (int b = 0; b < 4; ++b) {
            float4 x0 = __ldg(&other[(long long)c[b].x * F4 + f]);
            float4 x1 = __ldg(&other[(long long)c[b].y * F4 + f]);
            float4 x2 = __ldg(&other[(long long)c[b].z * F4 + f]);
            float4 x3 = __ldg(&other[(long long)c[b].w * F4 + f]);

            acc.x = fmaf(v[b].x, x0.x, acc.x);
            acc.y = fmaf(v[b].x, x0.y, acc.y);
            acc.z = fmaf(v[b].x, x0.z, acc.z);
            acc.w = fmaf(v[b].x, x0.w, acc.w);

            acc.x = fmaf(v[b].y, x1.x, acc.x);
            acc.y = fmaf(v[b].y, x1.y, acc.y);
            acc.z = fmaf(v[b].y, x1.z, acc.z);
            acc.w = fmaf(v[b].y, x1.w, acc.w);

            acc.x = fmaf(v[b].z, x2.x, acc.x);
            acc.y = fmaf(v[b].z, x2.y, acc.y);
            acc.z = fmaf(v[b].z, x2.z, acc.z);
            acc.w = fmaf(v[b].z, x2.w, acc.w);

            acc.x = fmaf(v[b].w, x3.x, acc.x);
            acc.y = fmaf(v[b].w, x3.y, acc.y);
            acc.z = fmaf(v[b].w, x3.z, acc.z);
            acc.w = fmaf(v[b].w, x3.w, acc.w);
        }
    } else {
        for (int e = start; e < start + deg; ++e) {
            const int   c = __ldg(&col[e]);
            const float v = __ldg(&value[e]);
            const float4 x = __ldg(&other[(long long)c * F4 + f]);
            acc.x = fmaf(v, x.x, acc.x);
            acc.y = fmaf(v, x.y, acc.y);
            acc.z = fmaf(v, x.z, acc.z);
            acc.w = fmaf(v, x.w, acc.w);
        }
    }

    out[(long long)row * F4 + f] = acc;
}

extern "C" void kernel_launch(void* const* d_in, const int* in_sizes, int n_in,
                              void* d_out, int out_size)
{
    // metadata order: rowptr (int32, N_ROWS+1), col (int32, E), value (f32, E), other (f32, N_COLS*F)
    const int*    rowptr = (const int*)d_in[0];
    const int*    col    = (const int*)d_in[1];
    const float*  value  = (const float*)d_in[2];
    const float4* other  = (const float4*)d_in[3];
    float4*       out    = (float4*)d_out;

    const int n_rows = in_sizes[0] - 1;

    dim3 block(F4, ROWS_PER_BLK);
    dim3 grid((n_rows + ROWS_PER_BLK - 1) / ROWS_PER_BLK);
    spmm_kernel<<<grid, block>>>(rowptr, col, value, other, out, n_rows);
}